// round 1
// baseline (speedup 1.0000x reference)
#include <cuda_runtime.h>

#define Nn 50000
#define Rr 16
#define Hh 32
#define Ll 8
#define Ee 1600000

// Scratch (static __device__ arrays: allocation-free per harness rules)
__device__ __align__(16) int   g_cnt[Rr * Nn];      // per-(relation,dst) edge counts
__device__ __align__(16) float g_h1[Nn * Hh];       // layer-1 hidden (agg -> relu'd)
__device__ __align__(16) float g_W2t[Rr * Ll * Hh]; // W2 transposed to [r][l][h]

// ---------------------------------------------------------------------------
// Zero all accumulators (d_out is poisoned to 0xAA by the harness)
// ---------------------------------------------------------------------------
__global__ void k_zero(float* __restrict__ out) {
    int i = blockIdx.x * blockDim.x + threadIdx.x;
    int stride = gridDim.x * blockDim.x;
    for (int j = i; j < Rr * Nn; j += stride) g_cnt[j] = 0;
    for (int j = i; j < Nn * Hh; j += stride) g_h1[j] = 0.0f;
    for (int j = i; j < Nn * Ll; j += stride) out[j] = 0.0f;
}

// ---------------------------------------------------------------------------
// Transpose W2 [r][h][l] -> [r][l][h] so layer-2 threads get contiguous f4 loads
// ---------------------------------------------------------------------------
__global__ void k_w2t(const float* __restrict__ W2) {
    int i = blockIdx.x * blockDim.x + threadIdx.x;
    if (i < Rr * Hh * Ll) {
        int r = i / (Hh * Ll);
        int rem = i - r * (Hh * Ll);
        int h = rem / Ll;
        int l = rem - h * Ll;
        g_W2t[(r * Ll + l) * Hh + h] = W2[i];
    }
}

// ---------------------------------------------------------------------------
// Per-(relation,dst) edge counts: seg = r*N + dst
// ---------------------------------------------------------------------------
__global__ void k_count(const int* __restrict__ et, const int* __restrict__ dst) {
    int e = blockIdx.x * blockDim.x + threadIdx.x;
    if (e < Ee) {
        atomicAdd(&g_cnt[et[e] * Nn + dst[e]], 1);
    }
}

// ---------------------------------------------------------------------------
// Layer 1: warp per edge.  lane = h.
//   g_h1[dst, h] += W1[r, src, h] * (1/max(cnt[r*N+dst],1))
// W1 row is one aligned 128B line -> single coalesced LDG.32 across the warp.
// ---------------------------------------------------------------------------
__global__ void k_layer1(const int* __restrict__ src, const int* __restrict__ dst,
                         const int* __restrict__ et, const float* __restrict__ W1) {
    int t = blockIdx.x * blockDim.x + threadIdx.x;
    int e = t >> 5;
    int lane = t & 31;
    if (e >= Ee) return;
    int s = __ldg(src + e);
    int d = __ldg(dst + e);
    int r = __ldg(et + e);
    float c = (float)g_cnt[r * Nn + d];
    float norm = 1.0f / fmaxf(c, 1.0f);
    float w = __ldg(W1 + ((r * Nn + s) * Hh + lane));
    atomicAdd(&g_h1[d * Hh + lane], w * norm);
}

// ---------------------------------------------------------------------------
// h1 = relu(agg1 + root1 + b1)
// ---------------------------------------------------------------------------
__global__ void k_relu(const float* __restrict__ root1, const float* __restrict__ b1) {
    int i = blockIdx.x * blockDim.x + threadIdx.x;
    if (i < Nn * Hh) {
        float v = g_h1[i] + root1[i] + b1[i & (Hh - 1)];
        g_h1[i] = v > 0.0f ? v : 0.0f;
    }
}

// ---------------------------------------------------------------------------
// Layer 2 edge pass: 8 threads per edge, thread l computes
//   y_l = sum_h h1[src,h] * W2[r,h,l]     (via transposed W2t[r][l][h])
//   out[dst,l] += norm * y_l
// h1 row: 8 lanes of the group load the SAME float4 -> L1 broadcast.
// W2t column: contiguous 32 floats -> 8x LDG.128, 16KB L1-resident.
// ---------------------------------------------------------------------------
__global__ void k_layer2(const int* __restrict__ src, const int* __restrict__ dst,
                         const int* __restrict__ et, float* __restrict__ out) {
    int t = blockIdx.x * blockDim.x + threadIdx.x;
    int e = t >> 3;
    int l = t & 7;
    if (e >= Ee) return;
    int s = __ldg(src + e);
    int d = __ldg(dst + e);
    int r = __ldg(et + e);
    float c = (float)g_cnt[r * Nn + d];
    float norm = 1.0f / fmaxf(c, 1.0f);

    const float4* hp = (const float4*)(g_h1 + s * Hh);
    const float4* wp = (const float4*)(g_W2t + (r * Ll + l) * Hh);

    float y = 0.0f;
#pragma unroll
    for (int j = 0; j < 8; j++) {
        float4 hv = hp[j];
        float4 wv = wp[j];
        y += hv.x * wv.x + hv.y * wv.y + hv.z * wv.z + hv.w * wv.w;
    }
    atomicAdd(&out[d * Ll + l], norm * y);
}

// ---------------------------------------------------------------------------
// Final: out[n,l] = sigmoid(edge_acc[n,l] + (h1[n,:] @ root2)[l] + b2[l])
// ---------------------------------------------------------------------------
__global__ void k_final(const float* __restrict__ root2, const float* __restrict__ b2,
                        float* __restrict__ out) {
    __shared__ float sR[Hh * Ll];
    __shared__ float sB[Ll];
    for (int i = threadIdx.x; i < Hh * Ll; i += blockDim.x) sR[i] = root2[i];
    if (threadIdx.x < Ll) sB[threadIdx.x] = b2[threadIdx.x];
    __syncthreads();

    int n = blockIdx.x * blockDim.x + threadIdx.x;
    if (n >= Nn) return;

    float y[Ll];
#pragma unroll
    for (int l = 0; l < Ll; l++) y[l] = sB[l];

    const float4* hp = (const float4*)(g_h1 + n * Hh);
#pragma unroll
    for (int j = 0; j < 8; j++) {
        float4 hv = hp[j];
        float hvals[4] = {hv.x, hv.y, hv.z, hv.w};
#pragma unroll
        for (int k = 0; k < 4; k++) {
            int h = j * 4 + k;
#pragma unroll
            for (int l = 0; l < Ll; l++) y[l] += hvals[k] * sR[h * Ll + l];
        }
    }

#pragma unroll
    for (int l = 0; l < Ll; l++) {
        float v = out[n * Ll + l] + y[l];
        out[n * Ll + l] = 1.0f / (1.0f + expf(-v));
    }
}

// ---------------------------------------------------------------------------
extern "C" void kernel_launch(void* const* d_in, const int* in_sizes, int n_in,
                              void* d_out, int out_size) {
    const int* ei    = (const int*)d_in[0];    // edge_index [2, E]
    const int* et    = (const int*)d_in[1];    // edge_type  [E]
    const float* W1  = (const float*)d_in[2];  // [R, N, H]
    const float* rt1 = (const float*)d_in[3];  // [N, H]
    const float* b1  = (const float*)d_in[4];  // [H]
    const float* W2  = (const float*)d_in[5];  // [R, H, L]
    const float* rt2 = (const float*)d_in[6];  // [H, L]
    const float* b2  = (const float*)d_in[7];  // [L]
    float* out = (float*)d_out;                // [N, L]

    const int* src = ei;
    const int* dst = ei + Ee;

    k_zero<<<2048, 256>>>(out);
    k_w2t<<<(Rr * Hh * Ll + 255) / 256, 256>>>(W2);
    k_count<<<(Ee + 255) / 256, 256>>>(et, dst);
    k_layer1<<<Ee / 8, 256>>>(src, dst, et, W1);   // 32 threads/edge
    k_relu<<<(Nn * Hh + 255) / 256, 256>>>(rt1, b1);
    k_layer2<<<Ee / 32, 256>>>(src, dst, et, out); // 8 threads/edge
    k_final<<<(Nn + 255) / 256, 256>>>(rt2, b2, out);
}